// round 16
// baseline (speedup 1.0000x reference)
#include <cuda_runtime.h>
#include <cuda_bf16.h>

// ---------------------------------------------------------------------------
// Transformer block with RBF x spherical-harmonic relative-position encoding.
// R15->R16: FFN GEMM M-tile 128->64 (4x4 microtile): grid 128->256 blocks so
// all 148 SMs are busy (was 20 idle SMs on the two longest kernels) and 2
// resident blocks/SM hide LDS latency. Same math, bitwise-identical results.
// ---------------------------------------------------------------------------

#define CUTOFF  10.0f
#define NRAD    64
#define NSPH    9
#define NHEADS  8
#define DMODEL  512
#define DHEAD   64
#define SEQL    256
#define NB      2
#define NROWS   (NB*SEQL)      // 512
#define NF      (NRAD*NSPH)    // 576
#define DFF     2048
#define KSPLIT  4

// bf16 vw layout: h-stride 656 elements. 1312B % 256 == 32: conflict-free.
#define VWB_H   656
#define VWB_ROW (NHEADS*VWB_H)  // 5248 bf16 per row (10496 B)
#define WS      260             // w_sm head stride

// k_scores dynamic smem layout (float words)
#define SC_VW   0
#define SC_W    (SC_VW + VWB_ROW/2)         // 2624
#define SC_G    (SC_W + NHEADS*WS)          // 4704
#define SC_SP   (SC_G + SEQL*16)            // 8800
#define SC_R0   (SC_SP + SEQL*12)           // 11872
#define SC_CB   (SC_R0 + SEQL)              // 12128
#define SC_MX   (SC_CB + NHEADS)            // 12136
#define SC_SUM  (SC_MX + NHEADS)            // 12144
#define SC_TOT  (SC_SUM + NHEADS)           // 12152 floats
#define SC_BYTES (SC_TOT * 4)               // 48608 B

__device__ __align__(16) __nv_bfloat16 g_vw[NROWS*VWB_ROW];
__device__ __align__(16) float g_base[NB*NHEADS*SEQL*SEQL];
__device__ __align__(16) float g_attn[NROWS*DMODEL];
__device__ __align__(16) float g_attn2[NROWS*DMODEL];
__device__ __align__(16) float g_x1[NROWS*DMODEL];
__device__ __align__(16) float g_hid[NROWS*DFF];
__device__ __align__(16) float g_yp[KSPLIT*NROWS*DMODEL];

// ---------------------------------------------------------------------------
// K1: fused prep. Blocks [0,576): vw (bf16 out). Blocks [576,832): base.
// ---------------------------------------------------------------------------
__global__ __launch_bounds__(256) void k_prep(const float* __restrict__ src,
                                              const float* __restrict__ rp_w) {
    __shared__ __align__(16) float As[64][64];   // [dh][row/l]
    __shared__ __align__(16) float Bs[64][64];   // [dh][f/m]
    const int id  = blockIdx.x;
    const int tid = threadIdx.x;
    const int tx = tid & 15, ty = tid >> 4;

    if (id < 576) {
        const int f0   = (id % 9) * 64;
        const int row0 = ((id / 9) & 7) * 64;
        const int h    = id / 72;
#pragma unroll
        for (int i = 0; i < 4; i++) {
            int lin = i * 256 + tid;
            int r   = lin >> 4;
            int k4  = lin & 15;
            float4 a = *(const float4*)&src [(row0 + r) * DMODEL + h * DHEAD + k4 * 4];
            As[k4*4+0][r] = a.x; As[k4*4+1][r] = a.y; As[k4*4+2][r] = a.z; As[k4*4+3][r] = a.w;
            float4 b = *(const float4*)&rp_w[(f0   + r) * DMODEL + h * DHEAD + k4 * 4];
            Bs[k4*4+0][r] = b.x; Bs[k4*4+1][r] = b.y; Bs[k4*4+2][r] = b.z; Bs[k4*4+3][r] = b.w;
        }
        __syncthreads();
        float acc[4][4] = {};
#pragma unroll
        for (int k = 0; k < 64; k++) {
            float a[4], b[4];
            *(float4*)a = *(const float4*)&As[k][ty * 4];
            *(float4*)b = *(const float4*)&Bs[k][tx * 4];
#pragma unroll
            for (int i = 0; i < 4; i++)
#pragma unroll
                for (int j = 0; j < 4; j++) acc[i][j] += a[i] * b[j];
        }
#pragma unroll
        for (int i = 0; i < 4; i++) {
            __nv_bfloat162 v01 = __floats2bfloat162_rn(acc[i][0], acc[i][1]);
            __nv_bfloat162 v23 = __floats2bfloat162_rn(acc[i][2], acc[i][3]);
            uint2 pk;
            pk.x = *reinterpret_cast<unsigned int*>(&v01);
            pk.y = *reinterpret_cast<unsigned int*>(&v23);
            *(uint2*)&g_vw[(row0 + ty*4 + i) * VWB_ROW + h * VWB_H + f0 + tx * 4] = pk;
        }
    } else {
        const int id2 = id - 576;
        const int m0 = (id2 & 3) * 64;
        const int l0 = ((id2 >> 2) & 3) * 64;
        const int b  = (id2 >> 4) >> 3;
        const int h  = (id2 >> 4) & 7;
        const float* sb = src + b * SEQL * DMODEL;
#pragma unroll
        for (int i = 0; i < 4; i++) {
            int lin = i * 256 + tid;
            int r   = lin >> 4;
            int k4  = lin & 15;
            float4 a = *(const float4*)&sb[(l0 + r) * DMODEL + h * DHEAD + k4 * 4];
            As[k4*4+0][r] = a.x; As[k4*4+1][r] = a.y; As[k4*4+2][r] = a.z; As[k4*4+3][r] = a.w;
            float4 c = *(const float4*)&sb[(m0 + r) * DMODEL + h * DHEAD + k4 * 4];
            Bs[k4*4+0][r] = c.x; Bs[k4*4+1][r] = c.y; Bs[k4*4+2][r] = c.z; Bs[k4*4+3][r] = c.w;
        }
        __syncthreads();
        float acc[4][4] = {};
#pragma unroll
        for (int k = 0; k < 64; k++) {
            float a[4], c[4];
            *(float4*)a = *(const float4*)&As[k][ty * 4];
            *(float4*)c = *(const float4*)&Bs[k][tx * 4];
#pragma unroll
            for (int i = 0; i < 4; i++)
#pragma unroll
                for (int j = 0; j < 4; j++) acc[i][j] += a[i] * c[j];
        }
#pragma unroll
        for (int i = 0; i < 4; i++) {
            float4 o = make_float4(acc[i][0]*0.125f, acc[i][1]*0.125f,
                                   acc[i][2]*0.125f, acc[i][3]*0.125f);
            *(float4*)&g_base[((b*NHEADS + h)*SEQL + l0 + ty*4 + i) * SEQL + m0 + tx*4] = o;
        }
    }
}

// ---------------------------------------------------------------------------
// K3: scores + softmax. vw in bf16 smem. Occupancy 4 -> single wave.
// ---------------------------------------------------------------------------
__global__ __launch_bounds__(256, 4) void k_scores(
    const float* __restrict__ src, const float* __restrict__ rp_b,
    const float* __restrict__ rel_diss, const float* __restrict__ rel_dirs) {
    extern __shared__ __align__(16) float sm[];
    int* r0s = (int*)&sm[SC_R0];
    const __nv_bfloat16* vwb = (const __nv_bfloat16*)&sm[SC_VW];

    const int row = blockIdx.x;
    const int b   = row >> 8;
    const int l   = row & 255;
    const int tid = threadIdx.x;
    const int wrp = tid >> 5, lane = tid & 31;

    {
        const uint4* vs = (const uint4*)&g_vw[row * VWB_ROW];
        uint4* vd = (uint4*)&sm[SC_VW];
        for (int i = tid; i < VWB_ROW / 8; i += 256) vd[i] = vs[i];
    }
#pragma unroll
    for (int h = 0; h < NHEADS; h++)
        sm[SC_W + h * WS + tid] = g_base[((b * NHEADS + h) * SEQL + l) * SEQL + tid];

    {
        const int m = tid;
        const float d  = rel_diss[row * SEQL + m];
        const float dx = rel_dirs[(row * SEQL + m) * 3 + 0];
        const float dy = rel_dirs[(row * SEQL + m) * 3 + 1];
        const float dz = rel_dirs[(row * SEQL + m) * 3 + 2];
        const float dc  = fminf(fmaxf(d * (1.0f / CUTOFF), 0.0f), 1.0f);
        const float env = 0.5f * (__cosf(3.14159265358979f * dc) + 1.0f);

        const float inv2w2 = 20.48f;
        const float cstep  = CUTOFF / 63.0f;
        int ic = (int)floorf(d * (63.0f / CUTOFF) + 0.5f);
        int r0 = (ic - 6) & ~3;
        r0 = min(max(r0, 0), NRAD - 16);
        r0s[m] = r0;
        const float base_d = d - (float)r0 * cstep;
#pragma unroll
        for (int j = 0; j < 16; j++) {
            float f = base_d - (float)j * cstep;
            sm[SC_G + m * 16 + j] = env * __expf(-f * f * inv2w2);
        }
        sm[SC_SP + m*12 + 0] = 0.28209479177387814f;
        sm[SC_SP + m*12 + 1] = 0.4886025119029199f * dy;
        sm[SC_SP + m*12 + 2] = 0.4886025119029199f * dz;
        sm[SC_SP + m*12 + 3] = 0.4886025119029199f * dx;
        sm[SC_SP + m*12 + 4] = 1.0925484305920792f * dx * dy;
        sm[SC_SP + m*12 + 5] = 1.0925484305920792f * dy * dz;
        sm[SC_SP + m*12 + 6] = 0.31539156525252005f * (3.0f * dz * dz - 1.0f);
        sm[SC_SP + m*12 + 7] = 1.0925484305920792f * dx * dz;
        sm[SC_SP + m*12 + 8] = 0.5462742152960396f * (dx * dx - dy * dy);
    }

    {
        float a = src[row * DMODEL + wrp * DHEAD + lane]      * rp_b[wrp * DHEAD + lane]
                + src[row * DMODEL + wrp * DHEAD + 32 + lane] * rp_b[wrp * DHEAD + 32 + lane];
#pragma unroll
        for (int o = 16; o > 0; o >>= 1) a += __shfl_xor_sync(0xffffffffu, a, o);
        if (lane == 0) sm[SC_CB + wrp] = a;
    }
    __syncthreads();

    const int hh = lane & 7, rq = lane >> 3;
    for (int i = 0; i < 32; i++) {
        const int m = i * 8 + wrp;
        const int r0 = r0s[m];
        const float4 ge = *(const float4*)&sm[SC_G + m * 16 + rq * 4];
        float spv[9];
        *(float4*)&spv[0] = *(const float4*)&sm[SC_SP + m * 12];
        *(float4*)&spv[4] = *(const float4*)&sm[SC_SP + m * 12 + 4];
        spv[8] = sm[SC_SP + m * 12 + 8];

        float ux = 0.0f, uy = 0.0f, uz = 0.0f, uw = 0.0f;
        const __nv_bfloat16* vp = &vwb[hh * VWB_H + r0 + rq * 4];
#pragma unroll
        for (int s = 0; s < NSPH; s++) {
            uint2 raw = *(const uint2*)&vp[s * NRAD];
            __nv_bfloat162 b01 = *reinterpret_cast<__nv_bfloat162*>(&raw.x);
            __nv_bfloat162 b23 = *reinterpret_cast<__nv_bfloat162*>(&raw.y);
            float2 f01 = __bfloat1622float2(b01);
            float2 f23 = __bfloat1622float2(b23);
            ux += spv[s] * f01.x; uy += spv[s] * f01.y;
            uz += spv[s] * f23.x; uw += spv[s] * f23.y;
        }
        float part = ge.x * ux + ge.y * uy + ge.z * uz + ge.w * uw;
        part += __shfl_xor_sync(0xffffffffu, part, 8);
        part += __shfl_xor_sync(0xffffffffu, part, 16);
        if (rq == 0)
            sm[SC_W + hh * WS + m] += part + sm[SC_CB + hh];
    }
    __syncthreads();

    {
        float mv = -1e30f;
#pragma unroll
        for (int i = 0; i < 8; i++) mv = fmaxf(mv, sm[SC_W + wrp * WS + lane + i * 32]);
#pragma unroll
        for (int o = 16; o > 0; o >>= 1) mv = fmaxf(mv, __shfl_xor_sync(0xffffffffu, mv, o));
        if (lane == 0) sm[SC_MX + wrp] = mv;
    }
    __syncthreads();
#pragma unroll
    for (int h = 0; h < NHEADS; h++)
        sm[SC_W + h * WS + tid] = __expf(sm[SC_W + h * WS + tid] - sm[SC_MX + h]);
    __syncthreads();
    {
        float sv = 0.0f;
#pragma unroll
        for (int i = 0; i < 8; i++) sv += sm[SC_W + wrp * WS + lane + i * 32];
#pragma unroll
        for (int o = 16; o > 0; o >>= 1) sv += __shfl_xor_sync(0xffffffffu, sv, o);
        if (lane == 0) sm[SC_SUM + wrp] = sv;
    }
    __syncthreads();
#pragma unroll
    for (int h = 0; h < NHEADS; h++) {
        float inv_s = 1.0f / sm[SC_SUM + h];
        g_base[((b * NHEADS + h) * SEQL + l) * SEQL + tid] = sm[SC_W + h * WS + tid] * inv_s;
    }
}

// ---------------------------------------------------------------------------
// K3b: attn = W @ V, double-buffered, m-split 2.
// ---------------------------------------------------------------------------
__global__ __launch_bounds__(256) void k_av(const float* __restrict__ src) {
    __shared__ float Ws[2][32][33];
    __shared__ float Vs[2][32][68];
    const int h    = blockIdx.x;
    const int l0   = blockIdx.y * 32;
    const int b    = blockIdx.z >> 1;
    const int half = blockIdx.z & 1;
    const int mb   = half * 128;
    const int tid = threadIdx.x;
    const int tx = tid & 15, ty = tid >> 4;
    const int r = tid >> 3, c = tid & 7;
    const float* W = g_base + ((b * NHEADS + h) * SEQL) * SEQL;
    const float* V = src + b * SEQL * DMODEL + h * DHEAD;

    float4 wv = *(const float4*)&W[(l0 + r) * SEQL + mb + c * 4];
    float4 v0 = *(const float4*)&V[(mb + r) * DMODEL + c * 8];
    float4 v1 = *(const float4*)&V[(mb + r) * DMODEL + c * 8 + 4];
    Ws[0][r][c*4+0] = wv.x; Ws[0][r][c*4+1] = wv.y;
    Ws[0][r][c*4+2] = wv.z; Ws[0][r][c*4+3] = wv.w;
    Vs[0][r][c*8+0] = v0.x; Vs[0][r][c*8+1] = v0.y;
    Vs[0][r][c*8+2] = v0.z; Vs[0][r][c*8+3] = v0.w;
    Vs[0][r][c*8+4] = v1.x; Vs[0][r][c*8+5] = v1.y;
    Vs[0][r][c*8+6] = v1.z; Vs[0][r][c*8+7] = v1.w;
    __syncthreads();

    float acc[2][4] = {};
#pragma unroll 1
    for (int mc = 0; mc < 4; mc++) {
        const int cur = mc & 1;
        if (mc + 1 < 4) {
            const int m0 = mb + (mc + 1) * 32;
            wv = *(const float4*)&W[(l0 + r) * SEQL + m0 + c * 4];
            v0 = *(const float4*)&V[(m0 + r) * DMODEL + c * 8];
            v1 = *(const float4*)&V[(m0 + r) * DMODEL + c * 8 + 4];
        }
#pragma unroll
        for (int k = 0; k < 32; k++) {
            float a0 = Ws[cur][ty][k];
            float a1 = Ws[cur][ty + 16][k];
            float4 bv = *(const float4*)&Vs[cur][k][tx * 4];
            acc[0][0] += a0 * bv.x; acc[0][1] += a0 * bv.y;
            acc[0][2] += a0 * bv.z; acc[0][3] += a0 * bv.w;
            acc[1][0] += a1 * bv.x; acc[1][1] += a1 * bv.y;
            acc[1][2] += a1 * bv.z; acc[1][3] += a1 * bv.w;
        }
        if (mc + 1 < 4) {
            const int nxt = cur ^ 1;
            Ws[nxt][r][c*4+0] = wv.x; Ws[nxt][r][c*4+1] = wv.y;
            Ws[nxt][r][c*4+2] = wv.z; Ws[nxt][r][c*4+3] = wv.w;
            Vs[nxt][r][c*8+0] = v0.x; Vs[nxt][r][c*8+1] = v0.y;
            Vs[nxt][r][c*8+2] = v0.z; Vs[nxt][r][c*8+3] = v0.w;
            Vs[nxt][r][c*8+4] = v1.x; Vs[nxt][r][c*8+5] = v1.y;
            Vs[nxt][r][c*8+6] = v1.z; Vs[nxt][r][c*8+7] = v1.w;
        }
        __syncthreads();
    }
    float* dst = half ? g_attn2 : g_attn;
#pragma unroll
    for (int i = 0; i < 2; i++) {
        float4 o = make_float4(acc[i][0], acc[i][1], acc[i][2], acc[i][3]);
        *(float4*)&dst[(b * SEQL + l0 + ty + i * 16) * DMODEL + h * DHEAD + tx * 4] = o;
    }
}

// ---------------------------------------------------------------------------
// K3c: x = LN1(src + attn0 + attn1). Warp-shuffle reduction.
// ---------------------------------------------------------------------------
__global__ __launch_bounds__(256) void k_ln1(const float* __restrict__ src,
                                             const float* __restrict__ gamma1,
                                             const float* __restrict__ beta1) {
    __shared__ float wsumA[8], wsumB[8];
    __shared__ float s_mu, s_rstd;
    const int row = blockIdx.x;
    const int tid = threadIdx.x;
    const int wrp = tid >> 5, lane = tid & 31;
    const int dd = 2 * tid;

    float2 s = *(const float2*)&src   [row * DMODEL + dd];
    float2 a = *(const float2*)&g_attn [row * DMODEL + dd];
    float2 a2= *(const float2*)&g_attn2[row * DMODEL + dd];
    float x0 = s.x + a.x + a2.x;
    float x1 = s.y + a.y + a2.y;

    float pA = x0 + x1;
    float pB = x0 * x0 + x1 * x1;
#pragma unroll
    for (int o = 16; o > 0; o >>= 1) {
        pA += __shfl_xor_sync(0xffffffffu, pA, o);
        pB += __shfl_xor_sync(0xffffffffu, pB, o);
    }
    if (lane == 0) { wsumA[wrp] = pA; wsumB[wrp] = pB; }
    __syncthreads();
    if (wrp == 0) {
        float tA = (lane < 8) ? wsumA[lane] : 0.0f;
        float tB = (lane < 8) ? wsumB[lane] : 0.0f;
#pragma unroll
        for (int o = 4; o > 0; o >>= 1) {
            tA += __shfl_xor_sync(0xffffffffu, tA, o);
            tB += __shfl_xor_sync(0xffffffffu, tB, o);
        }
        if (lane == 0) {
            float mu  = tA * (1.0f / DMODEL);
            float var = tB * (1.0f / DMODEL) - mu * mu;
            s_mu = mu;
            s_rstd = rsqrtf(var + 1e-5f);
        }
    }
    __syncthreads();
    const float mu = s_mu, rstd = s_rstd;
    float2 gm = *(const float2*)&gamma1[dd];
    float2 bt = *(const float2*)&beta1[dd];
    float2 o;
    o.x = (x0 - mu) * rstd * gm.x + bt.x;
    o.y = (x1 - mu) * rstd * gm.y + bt.y;
    *(float2*)&g_x1[row * DMODEL + dd] = o;
}

// ---------------------------------------------------------------------------
// K4: FFN GEMM1  g_hid = leaky_relu(g_x1 @ w1 + b1)
// 64x64 tile, 4x4 microtile, double-buffered, 1 barrier/chunk.
// grid (DFF/64=32, NROWS/64=8) = 256 blocks -> all SMs busy, 2 resident.
// ---------------------------------------------------------------------------
__global__ __launch_bounds__(256) void k_gemm1(const float* __restrict__ w1,
                                               const float* __restrict__ b1) {
    __shared__ __align__(16) float As[2][16][64];
    __shared__ __align__(16) float Bs[2][16][64];
    const int col0 = blockIdx.x * 64;
    const int row0 = blockIdx.y * 64;
    const int tid  = threadIdx.x;
    const int tx = tid & 15, ty = tid >> 4;
    const int ar = tid >> 2, akg = tid & 3;      // A: row ar (0..63), kg (0..3)
    const int bk = tid >> 4, bcg = tid & 15;     // B: k bk (0..15), col group

    const float* Ap = &g_x1[(row0 + ar) * DMODEL];
    const float* Bp = &w1[col0 + bcg * 4];

    float4 pa = *(const float4*)&Ap[akg * 4];
    float4 pb = *(const float4*)&Bp[bk * DFF];
    As[0][akg*4+0][ar] = pa.x; As[0][akg*4+1][ar] = pa.y;
    As[0][akg*4+2][ar] = pa.z; As[0][akg*4+3][ar] = pa.w;
    *(float4*)&Bs[0][bk][bcg * 4] = pb;
    __syncthreads();

    float acc[4][4] = {};
    const int NC = DMODEL / 16;                  // 32
#pragma unroll 1
    for (int c = 0; c < NC; c++) {
        const int cur = c & 1;
        if (c + 1 < NC) {
            const int k0 = (c + 1) * 16;
            pa = *(const float4*)&Ap[k0 + akg * 4];
            pb = *(const float4*)&Bp[(k0 + bk) * DFF];
        }
#pragma unroll
        for (int k = 0; k < 16; k++) {
            float a[4], bb[4];
            *(float4*)a  = *(const float4*)&As[cur][k][ty * 4];
            *(float4*)bb = *(const float4*)&Bs[cur][k][tx * 4];
#pragma unroll
            for (int i = 0; i < 4; i++)
#pragma unroll
                for (int j = 0; j < 4; j++) acc[i][j] += a[i] * bb[j];
        }
        if (c + 1 < NC) {
            const int nxt = cur ^ 1;
            As[nxt][akg*4+0][ar] = pa.x; As[nxt][akg*4+1][ar] = pa.y;
            As[nxt][akg*4+2][ar] = pa.z; As[nxt][akg*4+3][ar] = pa.w;
            *(float4*)&Bs[nxt][bk][bcg * 4] = pb;
        }
        __syncthreads();
    }

    float4 bv = *(const float4*)&b1[col0 + tx * 4];
#pragma unroll
    for (int i = 0; i < 4; i++) {
        float v0 = acc[i][0] + bv.x;
        float v1 = acc[i][1] + bv.y;
        float v2 = acc[i][2] + bv.z;
        float v3 = acc[i][3] + bv.w;
        float4 o;
        o.x = v0 > 0.0f ? v0 : 0.01f * v0;
        o.y = v1 > 0.0f ? v1 : 0.01f * v1;
        o.z = v2 > 0.0f ? v2 : 0.01f * v2;
        o.w = v3 > 0.0f ? v3 : 0.01f * v3;
        *(float4*)&g_hid[(row0 + ty * 4 + i) * DFF + col0 + tx * 4] = o;
    }
}

// ---------------------------------------------------------------------------
// K5: FFN GEMM2 (split-K=4 deterministic partials), 64x64 tiles.
// grid (DMODEL/64=8, NROWS/64=8, KSPLIT=4) = 256 blocks.
// ---------------------------------------------------------------------------
__global__ __launch_bounds__(256) void k_gemm2(const float* __restrict__ w2) {
    __shared__ __align__(16) float As[2][16][64];
    __shared__ __align__(16) float Bs[2][16][64];
    const int col0 = blockIdx.x * 64;
    const int row0 = blockIdx.y * 64;
    const int kz   = blockIdx.z;
    const int tid  = threadIdx.x;
    const int tx = tid & 15, ty = tid >> 4;
    const int ar = tid >> 2, akg = tid & 3;
    const int bk = tid >> 4, bcg = tid & 15;
    const int kbeg = kz * (DFF / KSPLIT);

    const float* Ap = &g_hid[(row0 + ar) * DFF + kbeg];
    const float* Bp = &w2[kbeg * DMODEL + col0 + bcg * 4];

    float4 pa = *(const float4*)&Ap[akg * 4];
    float4 pb = *(const float4*)&Bp[bk * DMODEL];
    As[0][akg*4+0][ar] = pa.x; As[0][akg*4+1][ar] = pa.y;
    As[0][akg*4+2][ar] = pa.z; As[0][akg*4+3][ar] = pa.w;
    *(float4*)&Bs[0][bk][bcg * 4] = pb;
    __syncthreads();

    float acc[4][4] = {};
    const int NC = (DFF / KSPLIT) / 16;          // 32
#pragma unroll 1
    for (int c = 0; c < NC; c++) {
        const int cur = c & 1;
        if (c + 1 < NC) {
            const int k0 = (c + 1) * 16;
            pa = *(const float4*)&Ap[k0 + akg * 4];
            pb = *(const float4*)&Bp[(k0 + bk) * DMODEL];
        }
#pragma unroll
        for (int k = 0; k < 16; k++) {
            float a[4], bb[4];
            *(float4*)a  = *(const float4*)&As[cur][k][ty * 4];
            *(float4*)bb = *(const float4*)&Bs[cur][k][tx * 4];
#pragma unroll
            for (int i = 0; i < 4; i++)
#pragma unroll
                for (int j = 0; j < 4; j++) acc[i][j] += a[i] * bb[j];
        }
        if (c + 1 < NC) {
            const int nxt = cur ^ 1;
            As[nxt][akg*4+0][ar] = pa.x; As[nxt][akg*4+1][ar] = pa.y;
            As[nxt][akg*4+2][ar] = pa.z; As[nxt][akg*4+3][ar] = pa.w;
            *(float4*)&Bs[nxt][bk][bcg * 4] = pb;
        }
        __syncthreads();
    }

#pragma unroll
    for (int i = 0; i < 4; i++) {
        float4 o = make_float4(acc[i][0], acc[i][1], acc[i][2], acc[i][3]);
        *(float4*)&g_yp[kz * NROWS * DMODEL + (row0 + ty * 4 + i) * DMODEL + col0 + tx * 4] = o;
    }
}

// ---------------------------------------------------------------------------
// K6: split-K combine + b2 + residual -> LN2 -> out. Warp-shuffle reduction.
// ---------------------------------------------------------------------------
__global__ __launch_bounds__(256) void k_ln2(const float* __restrict__ b2,
                                             const float* __restrict__ gamma2,
                                             const float* __restrict__ beta2,
                                             float* __restrict__ out) {
    __shared__ float wsumA[8], wsumB[8];
    __shared__ float s_mu, s_rstd;
    const int row = blockIdx.x;
    const int tid = threadIdx.x;
    const int wrp = tid >> 5, lane = tid & 31;
    const int dd = 2 * tid;

    float2 x = *(const float2*)&g_x1[row * DMODEL + dd];
    float2 bb = *(const float2*)&b2[dd];
    float y0 = x.x + bb.x;
    float y1 = x.y + bb.y;
#pragma unroll
    for (int kz = 0; kz < KSPLIT; kz++) {
        float2 p = *(const float2*)&g_yp[kz * NROWS * DMODEL + row * DMODEL + dd];
        y0 += p.x;
        y1 += p.y;
    }

    float pA = y0 + y1;
    float pB = y0 * y0 + y1 * y1;
#pragma unroll
    for (int o = 16; o > 0; o >>= 1) {
        pA += __shfl_xor_sync(0xffffffffu, pA, o);
        pB += __shfl_xor_sync(0xffffffffu, pB, o);
    }
    if (lane == 0) { wsumA[wrp] = pA; wsumB[wrp] = pB; }
    __syncthreads();
    if (wrp == 0) {
        float tA = (lane < 8) ? wsumA[lane] : 0.0f;
        float tB = (lane < 8) ? wsumB[lane] : 0.0f;
#pragma unroll
        for (int o = 4; o > 0; o >>= 1) {
            tA += __shfl_xor_sync(0xffffffffu, tA, o);
            tB += __shfl_xor_sync(0xffffffffu, tB, o);
        }
        if (lane == 0) {
            float mu  = tA * (1.0f / DMODEL);
            float var = tB * (1.0f / DMODEL) - mu * mu;
            s_mu = mu;
            s_rstd = rsqrtf(var + 1e-5f);
        }
    }
    __syncthreads();
    const float mu = s_mu, rstd = s_rstd;
    float2 gm = *(const float2*)&gamma2[dd];
    float2 bt = *(const float2*)&beta2[dd];
    float2 o;
    o.x = (y0 - mu) * rstd * gm.x + bt.x;
    o.y = (y1 - mu) * rstd * gm.y + bt.y;
    *(float2*)&out[row * DMODEL + dd] = o;
}

// ---------------------------------------------------------------------------
extern "C" void kernel_launch(void* const* d_in, const int* in_sizes, int n_in,
                              void* d_out, int out_size) {
    (void)in_sizes; (void)n_in; (void)out_size;
    const float* src      = (const float*)d_in[0];
    const float* rel_diss = (const float*)d_in[1];
    const float* rel_dirs = (const float*)d_in[2];
    const float* rp_w     = (const float*)d_in[3];
    const float* rp_b     = (const float*)d_in[4];
    const float* w1       = (const float*)d_in[5];
    const float* b1       = (const float*)d_in[6];
    const float* w2       = (const float*)d_in[7];
    const float* b2       = (const float*)d_in[8];
    const float* gamma1   = (const float*)d_in[9];
    const float* beta1    = (const float*)d_in[10];
    const float* gamma2   = (const float*)d_in[11];
    const float* beta2    = (const float*)d_in[12];
    float* out = (float*)d_out;

    // Unconditional (no static guards); idempotent, capture-legal.
    cudaFuncSetAttribute(k_scores,
                         cudaFuncAttributeMaxDynamicSharedMemorySize, SC_BYTES);

    k_prep  <<<832, 256>>>(src, rp_w);
    k_scores<<<NROWS, 256, SC_BYTES>>>(src, rp_b, rel_diss, rel_dirs);
    k_av    <<<dim3(NHEADS, SEQL/32, NB*2), 256>>>(src);
    k_ln1   <<<NROWS, 256>>>(src, gamma1, beta1);
    k_gemm1 <<<dim3(DFF/64, NROWS/64), 256>>>(w1, b1);
    k_gemm2 <<<dim3(DMODEL/64, NROWS/64, KSPLIT), 256>>>(w2);
    k_ln2   <<<NROWS, 256>>>(b2, gamma2, beta2, out);
}

// round 17
// speedup vs baseline: 1.0270x; 1.0270x over previous
#include <cuda_runtime.h>
#include <cuda_bf16.h>

// ---------------------------------------------------------------------------
// Transformer block with RBF x spherical-harmonic relative-position encoding.
// R16->R17: GEMMs reverted to R15 128x64 (actual best). k_prep exploits
// base's q.q^T symmetry (10 unique tiles per (b,h), transpose scatter-written
// from regs; base blocks 256->160). k_ln1/k_ln2 process 2 rows per block
// (grid 512->256) for doubled MLP on latency-bound LN kernels.
// ---------------------------------------------------------------------------

#define CUTOFF  10.0f
#define NRAD    64
#define NSPH    9
#define NHEADS  8
#define DMODEL  512
#define DHEAD   64
#define SEQL    256
#define NB      2
#define NROWS   (NB*SEQL)      // 512
#define NF      (NRAD*NSPH)    // 576
#define DFF     2048
#define KSPLIT  4

// bf16 vw layout: h-stride 656 elements. 1312B % 256 == 32: conflict-free.
#define VWB_H   656
#define VWB_ROW (NHEADS*VWB_H)  // 5248 bf16 per row (10496 B)
#define WS      260             // w_sm head stride

// k_scores dynamic smem layout (float words)
#define SC_VW   0
#define SC_W    (SC_VW + VWB_ROW/2)         // 2624
#define SC_G    (SC_W + NHEADS*WS)          // 4704
#define SC_SP   (SC_G + SEQL*16)            // 8800
#define SC_R0   (SC_SP + SEQL*12)           // 11872
#define SC_CB   (SC_R0 + SEQL)              // 12128
#define SC_MX   (SC_CB + NHEADS)            // 12136
#define SC_SUM  (SC_MX + NHEADS)            // 12144
#define SC_TOT  (SC_SUM + NHEADS)           // 12152 floats
#define SC_BYTES (SC_TOT * 4)               // 48608 B

__device__ __align__(16) __nv_bfloat16 g_vw[NROWS*VWB_ROW];
__device__ __align__(16) float g_base[NB*NHEADS*SEQL*SEQL];
__device__ __align__(16) float g_attn[NROWS*DMODEL];
__device__ __align__(16) float g_attn2[NROWS*DMODEL];
__device__ __align__(16) float g_x1[NROWS*DMODEL];
__device__ __align__(16) float g_hid[NROWS*DFF];
__device__ __align__(16) float g_yp[KSPLIT*NROWS*DMODEL];

// ---------------------------------------------------------------------------
// K1: fused prep. Blocks [0,576): vw (bf16 out).
// Blocks [576,736): base — 10 unique (l,m) tile pairs per (b,h) (symmetry);
// off-diagonal blocks also scatter-write the transposed tile.
// ---------------------------------------------------------------------------
__global__ __launch_bounds__(256) void k_prep(const float* __restrict__ src,
                                              const float* __restrict__ rp_w) {
    __shared__ __align__(16) float As[64][64];   // [dh][row/l]
    __shared__ __align__(16) float Bs[64][64];   // [dh][f/m]
    const int id  = blockIdx.x;
    const int tid = threadIdx.x;
    const int tx = tid & 15, ty = tid >> 4;

    if (id < 576) {
        const int f0   = (id % 9) * 64;
        const int row0 = ((id / 9) & 7) * 64;
        const int h    = id / 72;
#pragma unroll
        for (int i = 0; i < 4; i++) {
            int lin = i * 256 + tid;
            int r   = lin >> 4;
            int k4  = lin & 15;
            float4 a = *(const float4*)&src [(row0 + r) * DMODEL + h * DHEAD + k4 * 4];
            As[k4*4+0][r] = a.x; As[k4*4+1][r] = a.y; As[k4*4+2][r] = a.z; As[k4*4+3][r] = a.w;
            float4 b = *(const float4*)&rp_w[(f0   + r) * DMODEL + h * DHEAD + k4 * 4];
            Bs[k4*4+0][r] = b.x; Bs[k4*4+1][r] = b.y; Bs[k4*4+2][r] = b.z; Bs[k4*4+3][r] = b.w;
        }
        __syncthreads();
        float acc[4][4] = {};
#pragma unroll
        for (int k = 0; k < 64; k++) {
            float a[4], b[4];
            *(float4*)a = *(const float4*)&As[k][ty * 4];
            *(float4*)b = *(const float4*)&Bs[k][tx * 4];
#pragma unroll
            for (int i = 0; i < 4; i++)
#pragma unroll
                for (int j = 0; j < 4; j++) acc[i][j] += a[i] * b[j];
        }
#pragma unroll
        for (int i = 0; i < 4; i++) {
            __nv_bfloat162 v01 = __floats2bfloat162_rn(acc[i][0], acc[i][1]);
            __nv_bfloat162 v23 = __floats2bfloat162_rn(acc[i][2], acc[i][3]);
            uint2 pk;
            pk.x = *reinterpret_cast<unsigned int*>(&v01);
            pk.y = *reinterpret_cast<unsigned int*>(&v23);
            *(uint2*)&g_vw[(row0 + ty*4 + i) * VWB_ROW + h * VWB_H + f0 + tx * 4] = pk;
        }
    } else {
        const int id2 = id - 576;                 // 0..159
        const int p  = id2 % 10;
        const int bh = id2 / 10;                  // 0..15
        const int b  = bh >> 3, h = bh & 7;
        const int TL[10] = {0,0,0,0,1,1,1,2,2,3};
        const int TM[10] = {0,1,2,3,1,2,3,2,3,3};
        const int l0 = TL[p] * 64;
        const int m0 = TM[p] * 64;
        const float* sb = src + b * SEQL * DMODEL;
#pragma unroll
        for (int i = 0; i < 4; i++) {
            int lin = i * 256 + tid;
            int r   = lin >> 4;
            int k4  = lin & 15;
            float4 a = *(const float4*)&sb[(l0 + r) * DMODEL + h * DHEAD + k4 * 4];
            As[k4*4+0][r] = a.x; As[k4*4+1][r] = a.y; As[k4*4+2][r] = a.z; As[k4*4+3][r] = a.w;
            float4 c = *(const float4*)&sb[(m0 + r) * DMODEL + h * DHEAD + k4 * 4];
            Bs[k4*4+0][r] = c.x; Bs[k4*4+1][r] = c.y; Bs[k4*4+2][r] = c.z; Bs[k4*4+3][r] = c.w;
        }
        __syncthreads();
        float acc[4][4] = {};
#pragma unroll
        for (int k = 0; k < 64; k++) {
            float a[4], c[4];
            *(float4*)a = *(const float4*)&As[k][ty * 4];
            *(float4*)c = *(const float4*)&Bs[k][tx * 4];
#pragma unroll
            for (int i = 0; i < 4; i++)
#pragma unroll
                for (int j = 0; j < 4; j++) acc[i][j] += a[i] * c[j];
        }
        float* BB = g_base + (size_t)(b * NHEADS + h) * SEQL * SEQL;
#pragma unroll
        for (int i = 0; i < 4; i++) {
            float4 o = make_float4(acc[i][0]*0.125f, acc[i][1]*0.125f,
                                   acc[i][2]*0.125f, acc[i][3]*0.125f);
            *(float4*)&BB[(l0 + ty*4 + i) * SEQL + m0 + tx*4] = o;
        }
        if (l0 != m0) {                           // transposed tile (scatter)
#pragma unroll
            for (int j = 0; j < 4; j++)
#pragma unroll
                for (int i = 0; i < 4; i++)
                    BB[(m0 + tx*4 + j) * SEQL + l0 + ty*4 + i] = acc[i][j] * 0.125f;
        }
    }
}

// ---------------------------------------------------------------------------
// K3: scores + softmax. vw in bf16 smem. Occupancy 4 -> single wave.
// ---------------------------------------------------------------------------
__global__ __launch_bounds__(256, 4) void k_scores(
    const float* __restrict__ src, const float* __restrict__ rp_b,
    const float* __restrict__ rel_diss, const float* __restrict__ rel_dirs) {
    extern __shared__ __align__(16) float sm[];
    int* r0s = (int*)&sm[SC_R0];
    const __nv_bfloat16* vwb = (const __nv_bfloat16*)&sm[SC_VW];

    const int row = blockIdx.x;
    const int b   = row >> 8;
    const int l   = row & 255;
    const int tid = threadIdx.x;
    const int wrp = tid >> 5, lane = tid & 31;

    {
        const uint4* vs = (const uint4*)&g_vw[row * VWB_ROW];
        uint4* vd = (uint4*)&sm[SC_VW];
        for (int i = tid; i < VWB_ROW / 8; i += 256) vd[i] = vs[i];
    }
#pragma unroll
    for (int h = 0; h < NHEADS; h++)
        sm[SC_W + h * WS + tid] = g_base[((b * NHEADS + h) * SEQL + l) * SEQL + tid];

    {
        const int m = tid;
        const float d  = rel_diss[row * SEQL + m];
        const float dx = rel_dirs[(row * SEQL + m) * 3 + 0];
        const float dy = rel_dirs[(row * SEQL + m) * 3 + 1];
        const float dz = rel_dirs[(row * SEQL + m) * 3 + 2];
        const float dc  = fminf(fmaxf(d * (1.0f / CUTOFF), 0.0f), 1.0f);
        const float env = 0.5f * (__cosf(3.14159265358979f * dc) + 1.0f);

        const float inv2w2 = 20.48f;
        const float cstep  = CUTOFF / 63.0f;
        int ic = (int)floorf(d * (63.0f / CUTOFF) + 0.5f);
        int r0 = (ic - 6) & ~3;
        r0 = min(max(r0, 0), NRAD - 16);
        r0s[m] = r0;
        const float base_d = d - (float)r0 * cstep;
#pragma unroll
        for (int j = 0; j < 16; j++) {
            float f = base_d - (float)j * cstep;
            sm[SC_G + m * 16 + j] = env * __expf(-f * f * inv2w2);
        }
        sm[SC_SP + m*12 + 0] = 0.28209479177387814f;
        sm[SC_SP + m*12 + 1] = 0.4886025119029199f * dy;
        sm[SC_SP + m*12 + 2] = 0.4886025119029199f * dz;
        sm[SC_SP + m*12 + 3] = 0.4886025119029199f * dx;
        sm[SC_SP + m*12 + 4] = 1.0925484305920792f * dx * dy;
        sm[SC_SP + m*12 + 5] = 1.0925484305920792f * dy * dz;
        sm[SC_SP + m*12 + 6] = 0.31539156525252005f * (3.0f * dz * dz - 1.0f);
        sm[SC_SP + m*12 + 7] = 1.0925484305920792f * dx * dz;
        sm[SC_SP + m*12 + 8] = 0.5462742152960396f * (dx * dx - dy * dy);
    }

    {
        float a = src[row * DMODEL + wrp * DHEAD + lane]      * rp_b[wrp * DHEAD + lane]
                + src[row * DMODEL + wrp * DHEAD + 32 + lane] * rp_b[wrp * DHEAD + 32 + lane];
#pragma unroll
        for (int o = 16; o > 0; o >>= 1) a += __shfl_xor_sync(0xffffffffu, a, o);
        if (lane == 0) sm[SC_CB + wrp] = a;
    }
    __syncthreads();

    const int hh = lane & 7, rq = lane >> 3;
    for (int i = 0; i < 32; i++) {
        const int m = i * 8 + wrp;
        const int r0 = r0s[m];
        const float4 ge = *(const float4*)&sm[SC_G + m * 16 + rq * 4];
        float spv[9];
        *(float4*)&spv[0] = *(const float4*)&sm[SC_SP + m * 12];
        *(float4*)&spv[4] = *(const float4*)&sm[SC_SP + m * 12 + 4];
        spv[8] = sm[SC_SP + m * 12 + 8];

        float ux = 0.0f, uy = 0.0f, uz = 0.0f, uw = 0.0f;
        const __nv_bfloat16* vp = &vwb[hh * VWB_H + r0 + rq * 4];
#pragma unroll
        for (int s = 0; s < NSPH; s++) {
            uint2 raw = *(const uint2*)&vp[s * NRAD];
            __nv_bfloat162 b01 = *reinterpret_cast<__nv_bfloat162*>(&raw.x);
            __nv_bfloat162 b23 = *reinterpret_cast<__nv_bfloat162*>(&raw.y);
            float2 f01 = __bfloat1622float2(b01);
            float2 f23 = __bfloat1622float2(b23);
            ux += spv[s] * f01.x; uy += spv[s] * f01.y;
            uz += spv[s] * f23.x; uw += spv[s] * f23.y;
        }
        float part = ge.x * ux + ge.y * uy + ge.z * uz + ge.w * uw;
        part += __shfl_xor_sync(0xffffffffu, part, 8);
        part += __shfl_xor_sync(0xffffffffu, part, 16);
        if (rq == 0)
            sm[SC_W + hh * WS + m] += part + sm[SC_CB + hh];
    }
    __syncthreads();

    {
        float mv = -1e30f;
#pragma unroll
        for (int i = 0; i < 8; i++) mv = fmaxf(mv, sm[SC_W + wrp * WS + lane + i * 32]);
#pragma unroll
        for (int o = 16; o > 0; o >>= 1) mv = fmaxf(mv, __shfl_xor_sync(0xffffffffu, mv, o));
        if (lane == 0) sm[SC_MX + wrp] = mv;
    }
    __syncthreads();
#pragma unroll
    for (int h = 0; h < NHEADS; h++)
        sm[SC_W + h * WS + tid] = __expf(sm[SC_W + h * WS + tid] - sm[SC_MX + h]);
    __syncthreads();
    {
        float sv = 0.0f;
#pragma unroll
        for (int i = 0; i < 8; i++) sv += sm[SC_W + wrp * WS + lane + i * 32];
#pragma unroll
        for (int o = 16; o > 0; o >>= 1) sv += __shfl_xor_sync(0xffffffffu, sv, o);
        if (lane == 0) sm[SC_SUM + wrp] = sv;
    }
    __syncthreads();
#pragma unroll
    for (int h = 0; h < NHEADS; h++) {
        float inv_s = 1.0f / sm[SC_SUM + h];
        g_base[((b * NHEADS + h) * SEQL + l) * SEQL + tid] = sm[SC_W + h * WS + tid] * inv_s;
    }
}

// ---------------------------------------------------------------------------
// K3b: attn = W @ V, double-buffered, m-split 2.
// ---------------------------------------------------------------------------
__global__ __launch_bounds__(256) void k_av(const float* __restrict__ src) {
    __shared__ float Ws[2][32][33];
    __shared__ float Vs[2][32][68];
    const int h    = blockIdx.x;
    const int l0   = blockIdx.y * 32;
    const int b    = blockIdx.z >> 1;
    const int half = blockIdx.z & 1;
    const int mb   = half * 128;
    const int tid = threadIdx.x;
    const int tx = tid & 15, ty = tid >> 4;
    const int r = tid >> 3, c = tid & 7;
    const float* W = g_base + ((b * NHEADS + h) * SEQL) * SEQL;
    const float* V = src + b * SEQL * DMODEL + h * DHEAD;

    float4 wv = *(const float4*)&W[(l0 + r) * SEQL + mb + c * 4];
    float4 v0 = *(const float4*)&V[(mb + r) * DMODEL + c * 8];
    float4 v1 = *(const float4*)&V[(mb + r) * DMODEL + c * 8 + 4];
    Ws[0][r][c*4+0] = wv.x; Ws[0][r][c*4+1] = wv.y;
    Ws[0][r][c*4+2] = wv.z; Ws[0][r][c*4+3] = wv.w;
    Vs[0][r][c*8+0] = v0.x; Vs[0][r][c*8+1] = v0.y;
    Vs[0][r][c*8+2] = v0.z; Vs[0][r][c*8+3] = v0.w;
    Vs[0][r][c*8+4] = v1.x; Vs[0][r][c*8+5] = v1.y;
    Vs[0][r][c*8+6] = v1.z; Vs[0][r][c*8+7] = v1.w;
    __syncthreads();

    float acc[2][4] = {};
#pragma unroll 1
    for (int mc = 0; mc < 4; mc++) {
        const int cur = mc & 1;
        if (mc + 1 < 4) {
            const int m0 = mb + (mc + 1) * 32;
            wv = *(const float4*)&W[(l0 + r) * SEQL + m0 + c * 4];
            v0 = *(const float4*)&V[(m0 + r) * DMODEL + c * 8];
            v1 = *(const float4*)&V[(m0 + r) * DMODEL + c * 8 + 4];
        }
#pragma unroll
        for (int k = 0; k < 32; k++) {
            float a0 = Ws[cur][ty][k];
            float a1 = Ws[cur][ty + 16][k];
            float4 bv = *(const float4*)&Vs[cur][k][tx * 4];
            acc[0][0] += a0 * bv.x; acc[0][1] += a0 * bv.y;
            acc[0][2] += a0 * bv.z; acc[0][3] += a0 * bv.w;
            acc[1][0] += a1 * bv.x; acc[1][1] += a1 * bv.y;
            acc[1][2] += a1 * bv.z; acc[1][3] += a1 * bv.w;
        }
        if (mc + 1 < 4) {
            const int nxt = cur ^ 1;
            Ws[nxt][r][c*4+0] = wv.x; Ws[nxt][r][c*4+1] = wv.y;
            Ws[nxt][r][c*4+2] = wv.z; Ws[nxt][r][c*4+3] = wv.w;
            Vs[nxt][r][c*8+0] = v0.x; Vs[nxt][r][c*8+1] = v0.y;
            Vs[nxt][r][c*8+2] = v0.z; Vs[nxt][r][c*8+3] = v0.w;
            Vs[nxt][r][c*8+4] = v1.x; Vs[nxt][r][c*8+5] = v1.y;
            Vs[nxt][r][c*8+6] = v1.z; Vs[nxt][r][c*8+7] = v1.w;
        }
        __syncthreads();
    }
    float* dst = half ? g_attn2 : g_attn;
#pragma unroll
    for (int i = 0; i < 2; i++) {
        float4 o = make_float4(acc[i][0], acc[i][1], acc[i][2], acc[i][3]);
        *(float4*)&dst[(b * SEQL + l0 + ty + i * 16) * DMODEL + h * DHEAD + tx * 4] = o;
    }
}

// ---------------------------------------------------------------------------
// K3c: x = LN1(src + attn0 + attn1). 2 rows per block, shuffle reductions.
// ---------------------------------------------------------------------------
__global__ __launch_bounds__(256) void k_ln1(const float* __restrict__ src,
                                             const float* __restrict__ gamma1,
                                             const float* __restrict__ beta1) {
    __shared__ float ws[4][8];
    __shared__ float s_stat[4];     // mu0, rstd0, mu1, rstd1
    const int row0 = blockIdx.x * 2;
    const int tid  = threadIdx.x;
    const int wrp = tid >> 5, lane = tid & 31;
    const int dd = 2 * tid;

    float2 s0 = *(const float2*)&src    [row0 * DMODEL + dd];
    float2 a0 = *(const float2*)&g_attn [row0 * DMODEL + dd];
    float2 c0 = *(const float2*)&g_attn2[row0 * DMODEL + dd];
    float2 s1 = *(const float2*)&src    [(row0+1) * DMODEL + dd];
    float2 a1 = *(const float2*)&g_attn [(row0+1) * DMODEL + dd];
    float2 c1 = *(const float2*)&g_attn2[(row0+1) * DMODEL + dd];
    float x00 = s0.x + a0.x + c0.x, x01 = s0.y + a0.y + c0.y;
    float x10 = s1.x + a1.x + c1.x, x11 = s1.y + a1.y + c1.y;

    float pA0 = x00 + x01, pB0 = x00*x00 + x01*x01;
    float pA1 = x10 + x11, pB1 = x10*x10 + x11*x11;
#pragma unroll
    for (int o = 16; o > 0; o >>= 1) {
        pA0 += __shfl_xor_sync(0xffffffffu, pA0, o);
        pB0 += __shfl_xor_sync(0xffffffffu, pB0, o);
        pA1 += __shfl_xor_sync(0xffffffffu, pA1, o);
        pB1 += __shfl_xor_sync(0xffffffffu, pB1, o);
    }
    if (lane == 0) {
        ws[0][wrp] = pA0; ws[1][wrp] = pB0;
        ws[2][wrp] = pA1; ws[3][wrp] = pB1;
    }
    __syncthreads();
    if (wrp == 0 && lane < 16) {
        int which = lane >> 3;           // 0: row0, 1: row1
        int ln = lane & 7;
        float tA = ws[which*2][ln];
        float tB = ws[which*2+1][ln];
#pragma unroll
        for (int o = 4; o > 0; o >>= 1) {
            tA += __shfl_xor_sync(0x0000ffffu, tA, o);
            tB += __shfl_xor_sync(0x0000ffffu, tB, o);
        }
        if (ln == 0) {
            float mu  = tA * (1.0f / DMODEL);
            float var = tB * (1.0f / DMODEL) - mu * mu;
            s_stat[which*2]   = mu;
            s_stat[which*2+1] = rsqrtf(var + 1e-5f);
        }
    }
    __syncthreads();
    float2 gm = *(const float2*)&gamma1[dd];
    float2 bt = *(const float2*)&beta1[dd];
    {
        float mu = s_stat[0], rstd = s_stat[1];
        float2 o;
        o.x = (x00 - mu) * rstd * gm.x + bt.x;
        o.y = (x01 - mu) * rstd * gm.y + bt.y;
        *(float2*)&g_x1[row0 * DMODEL + dd] = o;
    }
    {
        float mu = s_stat[2], rstd = s_stat[3];
        float2 o;
        o.x = (x10 - mu) * rstd * gm.x + bt.x;
        o.y = (x11 - mu) * rstd * gm.y + bt.y;
        *(float2*)&g_x1[(row0+1) * DMODEL + dd] = o;
    }
}

// ---------------------------------------------------------------------------
// K4: FFN GEMM1  g_hid = leaky_relu(g_x1 @ w1 + b1)   (R15/best config)
// ---------------------------------------------------------------------------
__global__ __launch_bounds__(256) void k_gemm1(const float* __restrict__ w1,
                                               const float* __restrict__ b1) {
    __shared__ __align__(16) float As[2][16][128];
    __shared__ __align__(16) float Bs[2][16][64];
    const int col0 = blockIdx.x * 64;
    const int row0 = blockIdx.y * 128;
    const int tid  = threadIdx.x;
    const int tx = tid & 15, ty = tid >> 4;
    const int ar = tid & 127, akg = tid >> 7;
    const int bk = tid >> 4, bcg = tid & 15;

    const float* Ap = &g_x1[(row0 + ar) * DMODEL];
    const float* Bp = &w1[col0 + bcg * 4];

    float4 pa0 = *(const float4*)&Ap[akg * 4];
    float4 pa1 = *(const float4*)&Ap[(akg + 2) * 4];
    float4 pb  = *(const float4*)&Bp[bk * DFF];
    As[0][akg*4+0][ar] = pa0.x; As[0][akg*4+1][ar] = pa0.y;
    As[0][akg*4+2][ar] = pa0.z; As[0][akg*4+3][ar] = pa0.w;
    As[0][akg*4+8][ar] = pa1.x; As[0][akg*4+9][ar] = pa1.y;
    As[0][akg*4+10][ar] = pa1.z; As[0][akg*4+11][ar] = pa1.w;
    *(float4*)&Bs[0][bk][bcg * 4] = pb;
    __syncthreads();

    float acc[8][4] = {};
    const int NC = DMODEL / 16;
#pragma unroll 1
    for (int c = 0; c < NC; c++) {
        const int cur = c & 1;
        if (c + 1 < NC) {
            const int k0 = (c + 1) * 16;
            pa0 = *(const float4*)&Ap[k0 + akg * 4];
            pa1 = *(const float4*)&Ap[k0 + (akg + 2) * 4];
            pb  = *(const float4*)&Bp[(k0 + bk) * DFF];
        }
#pragma unroll
        for (int k = 0; k < 16; k++) {
            float a[8], bb[4];
            *(float4*)&a[0] = *(const float4*)&As[cur][k][ty * 8];
            *(float4*)&a[4] = *(const float4*)&As[cur][k][ty * 8 + 4];
            *(float4*)&bb[0] = *(const float4*)&Bs[cur][k][tx * 4];
#pragma unroll
            for (int i = 0; i < 8; i++)
#pragma unroll
                for (int j = 0; j < 4; j++) acc[i][j] += a[i] * bb[j];
        }
        if (c + 1 < NC) {
            const int nxt = cur ^ 1;
            As[nxt][akg*4+0][ar] = pa0.x; As[nxt][akg*4+1][ar] = pa0.y;
            As[nxt][akg*4+2][ar] = pa0.z; As[nxt][akg*4+3][ar] = pa0.w;
            As[nxt][akg*4+8][ar] = pa1.x; As[nxt][akg*4+9][ar] = pa1.y;
            As[nxt][akg*4+10][ar] = pa1.z; As[nxt][akg*4+11][ar] = pa1.w;
            *(float4*)&Bs[nxt][bk][bcg * 4] = pb;
        }
        __syncthreads();
    }

    float4 bv = *(const float4*)&b1[col0 + tx * 4];
#pragma unroll
    for (int i = 0; i < 8; i++) {
        float v0 = acc[i][0] + bv.x;
        float v1 = acc[i][1] + bv.y;
        float v2 = acc[i][2] + bv.z;
        float v3 = acc[i][3] + bv.w;
        float4 o;
        o.x = v0 > 0.0f ? v0 : 0.01f * v0;
        o.y = v1 > 0.0f ? v1 : 0.01f * v1;
        o.z = v2 > 0.0f ? v2 : 0.01f * v2;
        o.w = v3 > 0.0f ? v3 : 0.01f * v3;
        *(float4*)&g_hid[(row0 + ty * 8 + i) * DFF + col0 + tx * 4] = o;
    }
}

// ---------------------------------------------------------------------------
// K5: FFN GEMM2 (split-K=4 deterministic partials)   (R15/best config)
// ---------------------------------------------------------------------------
__global__ __launch_bounds__(256) void k_gemm2(const float* __restrict__ w2) {
    __shared__ __align__(16) float As[2][16][128];
    __shared__ __align__(16) float Bs[2][16][64];
    const int col0 = blockIdx.x * 64;
    const int row0 = blockIdx.y * 128;
    const int kz   = blockIdx.z;
    const int tid  = threadIdx.x;
    const int tx = tid & 15, ty = tid >> 4;
    const int ar = tid & 127, akg = tid >> 7;
    const int bk = tid >> 4, bcg = tid & 15;
    const int kbeg = kz * (DFF / KSPLIT);

    const float* Ap = &g_hid[(row0 + ar) * DFF + kbeg];
    const float* Bp = &w2[kbeg * DMODEL + col0 + bcg * 4];

    float4 pa0 = *(const float4*)&Ap[akg * 4];
    float4 pa1 = *(const float4*)&Ap[(akg + 2) * 4];
    float4 pb  = *(const float4*)&Bp[bk * DMODEL];
    As[0][akg*4+0][ar] = pa0.x; As[0][akg*4+1][ar] = pa0.y;
    As[0][akg*4+2][ar] = pa0.z; As[0][akg*4+3][ar] = pa0.w;
    As[0][akg*4+8][ar] = pa1.x; As[0][akg*4+9][ar] = pa1.y;
    As[0][akg*4+10][ar] = pa1.z; As[0][akg*4+11][ar] = pa1.w;
    *(float4*)&Bs[0][bk][bcg * 4] = pb;
    __syncthreads();

    float acc[8][4] = {};
    const int NC = (DFF / KSPLIT) / 16;
#pragma unroll 1
    for (int c = 0; c < NC; c++) {
        const int cur = c & 1;
        if (c + 1 < NC) {
            const int k0 = (c + 1) * 16;
            pa0 = *(const float4*)&Ap[k0 + akg * 4];
            pa1 = *(const float4*)&Ap[k0 + (akg + 2) * 4];
            pb  = *(const float4*)&Bp[(k0 + bk) * DMODEL];
        }
#pragma unroll
        for (int k = 0; k < 16; k++) {
            float a[8], bb[4];
            *(float4*)&a[0] = *(const float4*)&As[cur][k][ty * 8];
            *(float4*)&a[4] = *(const float4*)&As[cur][k][ty * 8 + 4];
            *(float4*)&bb[0] = *(const float4*)&Bs[cur][k][tx * 4];
#pragma unroll
            for (int i = 0; i < 8; i++)
#pragma unroll
                for (int j = 0; j < 4; j++) acc[i][j] += a[i] * bb[j];
        }
        if (c + 1 < NC) {
            const int nxt = cur ^ 1;
            As[nxt][akg*4+0][ar] = pa0.x; As[nxt][akg*4+1][ar] = pa0.y;
            As[nxt][akg*4+2][ar] = pa0.z; As[nxt][akg*4+3][ar] = pa0.w;
            As[nxt][akg*4+8][ar] = pa1.x; As[nxt][akg*4+9][ar] = pa1.y;
            As[nxt][akg*4+10][ar] = pa1.z; As[nxt][akg*4+11][ar] = pa1.w;
            *(float4*)&Bs[nxt][bk][bcg * 4] = pb;
        }
        __syncthreads();
    }

#pragma unroll
    for (int i = 0; i < 8; i++) {
        float4 o = make_float4(acc[i][0], acc[i][1], acc[i][2], acc[i][3]);
        *(float4*)&g_yp[kz * NROWS * DMODEL + (row0 + ty * 8 + i) * DMODEL + col0 + tx * 4] = o;
    }
}

// ---------------------------------------------------------------------------
// K6: split-K combine + b2 + residual -> LN2 -> out. 2 rows per block.
// ---------------------------------------------------------------------------
__global__ __launch_bounds__(256) void k_ln2(const float* __restrict__ b2,
                                             const float* __restrict__ gamma2,
                                             const float* __restrict__ beta2,
                                             float* __restrict__ out) {
    __shared__ float ws[4][8];
    __shared__ float s_stat[4];
    const int row0 = blockIdx.x * 2;
    const int tid  = threadIdx.x;
    const int wrp = tid >> 5, lane = tid & 31;
    const int dd = 2 * tid;

    float2 bb = *(const float2*)&b2[dd];
    float2 x0 = *(const float2*)&g_x1[row0 * DMODEL + dd];
    float2 x1 = *(const float2*)&g_x1[(row0+1) * DMODEL + dd];
    float y00 = x0.x + bb.x, y01 = x0.y + bb.y;
    float y10 = x1.x + bb.x, y11 = x1.y + bb.y;
#pragma unroll
    for (int kz = 0; kz < KSPLIT; kz++) {
        float2 p0 = *(const float2*)&g_yp[kz * NROWS * DMODEL + row0 * DMODEL + dd];
        float2 p1 = *(const float2*)&g_yp[kz * NROWS * DMODEL + (row0+1) * DMODEL + dd];
        y00 += p0.x; y01 += p0.y;
        y10 += p1.x; y11 += p1.y;
    }

    float pA0 = y00 + y01, pB0 = y00*y00 + y01*y01;
    float pA1 = y10 + y11, pB1 = y10*y10 + y11*y11;
#pragma unroll
    for (int o = 16; o > 0; o >>= 1) {
        pA0 += __shfl_xor_sync(0xffffffffu, pA0, o);
        pB0 += __shfl_xor_sync(0xffffffffu, pB0, o);
        pA1 += __shfl_xor_sync(0xffffffffu, pA1, o);
        pB1 += __shfl_xor_sync(0xffffffffu, pB1, o);
    }
    if (lane == 0) {
        ws[0][wrp] = pA0; ws[1][wrp] = pB0;
        ws[2][wrp] = pA1; ws[3][wrp] = pB1;
    }
    __syncthreads();
    if (wrp == 0 && lane < 16) {
        int which = lane >> 3;
        int ln = lane & 7;
        float tA = ws[which*2][ln];
        float tB = ws[which*2+1][ln];
#pragma unroll
        for (int o = 4; o > 0; o >>= 1) {
            tA += __shfl_xor_sync(0x0000ffffu, tA, o);
            tB += __shfl_xor_sync(0x0000ffffu, tB, o);
        }
        if (ln == 0) {
            float mu  = tA * (1.0f / DMODEL);
            float var = tB * (1.0f / DMODEL) - mu * mu;
            s_stat[which*2]   = mu;
            s_stat[which*2+1] = rsqrtf(var + 1e-5f);
        }
    }
    __syncthreads();
    float2 gm = *(const float2*)&gamma2[dd];
    float2 bt = *(const float2*)&beta2[dd];
    {
        float mu = s_stat[0], rstd = s_stat[1];
        float2 o;
        o.x = (y00 - mu) * rstd * gm.x + bt.x;
        o.y = (y01 - mu) * rstd * gm.y + bt.y;
        *(float2*)&out[row0 * DMODEL + dd] = o;
    }
    {
        float mu = s_stat[2], rstd = s_stat[3];
        float2 o;
        o.x = (y10 - mu) * rstd * gm.x + bt.x;
        o.y = (y11 - mu) * rstd * gm.y + bt.y;
        *(float2*)&out[(row0+1) * DMODEL + dd] = o;
    }
}

// ---------------------------------------------------------------------------
extern "C" void kernel_launch(void* const* d_in, const int* in_sizes, int n_in,
                              void* d_out, int out_size) {
    (void)in_sizes; (void)n_in; (void)out_size;
    const float* src      = (const float*)d_in[0];
    const float* rel_diss = (const float*)d_in[1];
    const float* rel_dirs = (const float*)d_in[2];
    const float* rp_w     = (const float*)d_in[3];
    const float* rp_b     = (const float*)d_in[4];
    const float* w1       = (const float*)d_in[5];
    const float* b1       = (const float*)d_in[6];
    const float* w2       = (const float*)d_in[7];
    const float* b2       = (const float*)d_in[8];
    const float* gamma1   = (const float*)d_in[9];
    const float* beta1    = (const float*)d_in[10];
    const float* gamma2   = (const float*)d_in[11];
    const float* beta2    = (const float*)d_in[12];
    float* out = (float*)d_out;

    // Unconditional (no static guards); idempotent, capture-legal.
    cudaFuncSetAttribute(k_scores,
                         cudaFuncAttributeMaxDynamicSharedMemorySize, SC_BYTES);

    k_prep  <<<736, 256>>>(src, rp_w);
    k_scores<<<NROWS, 256, SC_BYTES>>>(src, rp_b, rel_diss, rel_dirs);
    k_av    <<<dim3(NHEADS, SEQL/32, NB*2), 256>>>(src);
    k_ln1   <<<NROWS/2, 256>>>(src, gamma1, beta1);
    k_gemm1 <<<dim3(DFF/64, NROWS/128), 256>>>(w1, b1);
    k_gemm2 <<<dim3(DMODEL/64, NROWS/128, KSPLIT), 256>>>(w2);
    k_ln2   <<<NROWS/2, 256>>>(b2, gamma2, beta2, out);
}